// round 1
// baseline (speedup 1.0000x reference)
#include <cuda_runtime.h>
#include <math.h>

// Problem constants
#define kT 4096
#define kE 1024
#define kH 16
#define kD 64

// Scratch (allocation-free rule: __device__ globals)
__device__ float g_q[kT * kE];
__device__ float g_k[kT * kE];
__device__ float g_v[kT * kE];
__device__ float g_attn[kT * kE];

// ---------------------------------------------------------------------------
// GEMM-NT with bias: Y[t,o] = sum_i X[t,i] * W[o,i] + b[o]
// X: [Trows, kE] row-major, W: [Ocols, kE] row-major (torch Linear weight)
// Block tile 128x128, K-chunk 16, 256 threads, 8x8 per thread.
// ---------------------------------------------------------------------------
__global__ __launch_bounds__(256, 2)
void gemm_nt_bias(const float* __restrict__ X, const float* __restrict__ W,
                  const float* __restrict__ bias, float* __restrict__ Y) {
    __shared__ float As[16][128];   // k-major: As[kk][row]
    __shared__ float Bs[16][128];   // k-major: Bs[kk][col]

    const int tid = threadIdx.x;
    const int tx = tid & 15;        // 0..15 -> output cols tx*8..tx*8+7
    const int ty = tid >> 4;        // 0..15 -> output rows ty*8..ty*8+7
    const int row0 = blockIdx.y * 128;
    const int col0 = blockIdx.x * 128;

    float acc[8][8];
#pragma unroll
    for (int i = 0; i < 8; i++)
#pragma unroll
        for (int j = 0; j < 8; j++) acc[i][j] = 0.0f;

    const float* Xp = X + (size_t)row0 * kE;
    const float* Wp = W + (size_t)col0 * kE;

    for (int k0 = 0; k0 < kE; k0 += 16) {
#pragma unroll
        for (int i = 0; i < 2; i++) {
            int f = tid + i * 256;      // 0..511
            int r = f >> 2;             // 0..127
            int c4 = (f & 3) << 2;      // 0,4,8,12
            float4 xa = *(const float4*)(Xp + (size_t)r * kE + k0 + c4);
            As[c4 + 0][r] = xa.x;
            As[c4 + 1][r] = xa.y;
            As[c4 + 2][r] = xa.z;
            As[c4 + 3][r] = xa.w;
            float4 wb = *(const float4*)(Wp + (size_t)r * kE + k0 + c4);
            Bs[c4 + 0][r] = wb.x;
            Bs[c4 + 1][r] = wb.y;
            Bs[c4 + 2][r] = wb.z;
            Bs[c4 + 3][r] = wb.w;
        }
        __syncthreads();

#pragma unroll
        for (int kk = 0; kk < 16; kk++) {
            float a[8], b[8];
            *(float4*)&a[0] = *(const float4*)&As[kk][ty * 8];
            *(float4*)&a[4] = *(const float4*)&As[kk][ty * 8 + 4];
            *(float4*)&b[0] = *(const float4*)&Bs[kk][tx * 8];
            *(float4*)&b[4] = *(const float4*)&Bs[kk][tx * 8 + 4];
#pragma unroll
            for (int i = 0; i < 8; i++)
#pragma unroll
                for (int j = 0; j < 8; j++)
                    acc[i][j] = fmaf(a[i], b[j], acc[i][j]);
        }
        __syncthreads();
    }

    // Epilogue: add bias, vectorized stores
#pragma unroll
    for (int i = 0; i < 8; i++) {
        int r = row0 + ty * 8 + i;
        float* yp = Y + (size_t)r * kE + col0 + tx * 8;
        const float* bp = bias + col0 + tx * 8;
#pragma unroll
        for (int j4 = 0; j4 < 2; j4++) {
            float4 v;
            v.x = acc[i][j4 * 4 + 0] + bp[j4 * 4 + 0];
            v.y = acc[i][j4 * 4 + 1] + bp[j4 * 4 + 1];
            v.z = acc[i][j4 * 4 + 2] + bp[j4 * 4 + 2];
            v.w = acc[i][j4 * 4 + 3] + bp[j4 * 4 + 3];
            *(float4*)(yp + j4 * 4) = v;
        }
    }
}

// ---------------------------------------------------------------------------
// Varlen flash attention.
// Grid: (kT/64 q-tiles, kH heads). Block: 256 threads (16x16), each 4x4.
// Per-row segment bounds from cu_seqlens computed on device.
// Online softmax with finite -1e30 sentinel (matches reference NEG mask).
// ---------------------------------------------------------------------------
#define ATTN_SMEM_BYTES (3 * 4096 * 4 + 64 * 68 * 4 + 2 * 64 * 4)  // 67072

__global__ __launch_bounds__(256, 1)
void varlen_attn(const float* __restrict__ Q, const float* __restrict__ K,
                 const float* __restrict__ V, const int* __restrict__ cu,
                 float* __restrict__ Out) {
    extern __shared__ float sm[];
    float* Qs = sm;                  // [64 d][64 q]  (d-major, transposed)
    float* Ks = sm + 4096;           // [64 d][64 k]
    float* Vs = sm + 8192;           // [64 k][64 d]  (natural)
    float* Ps = sm + 12288;          // [64 q][68]    (padded row)
    int* s_lo = (int*)(sm + 12288 + 64 * 68);
    int* s_hi = s_lo + 64;

    const int tid = threadIdx.x;
    const int tx = tid & 15;
    const int ty = tid >> 4;
    const int q0 = blockIdx.x * 64;
    const int hcol = blockIdx.y * kD;

    // Per-q-row segment bounds
    if (tid < 64) {
        int r = q0 + tid;
        int lo = 0, hi = kT;
#pragma unroll
        for (int s = 0; s < 8; s++) {
            int a = cu[s], b = cu[s + 1];
            if (r >= a && r < b) { lo = a; hi = b; }
        }
        s_lo[tid] = lo;
        s_hi[tid] = hi;
    }

    // Load Q tile (pre-scaled by D^-0.5 = 0.125), transpose into d-major
#pragma unroll
    for (int i = 0; i < 4; i++) {
        int f4 = tid + i * 256;       // 0..1023 float4-slots
        int r = f4 >> 4;              // 0..63
        int d = (f4 & 15) << 2;       // 0..60
        float4 qv = *(const float4*)(Q + (size_t)(q0 + r) * kE + hcol + d);
        Qs[(d + 0) * 64 + r] = qv.x * 0.125f;
        Qs[(d + 1) * 64 + r] = qv.y * 0.125f;
        Qs[(d + 2) * 64 + r] = qv.z * 0.125f;
        Qs[(d + 3) * 64 + r] = qv.w * 0.125f;
    }
    __syncthreads();

    int row_lo[4], row_hi[4];
#pragma unroll
    for (int i = 0; i < 4; i++) {
        row_lo[i] = s_lo[ty * 4 + i];
        row_hi[i] = s_hi[ty * 4 + i];
    }
    const int span_lo = s_lo[0];
    const int span_hi = s_hi[63];

    float m[4], l[4], o[4][4];
#pragma unroll
    for (int i = 0; i < 4; i++) {
        m[i] = -1e30f;
        l[i] = 0.0f;
#pragma unroll
        for (int j = 0; j < 4; j++) o[i][j] = 0.0f;
    }

    for (int kb = span_lo; kb < span_hi; kb += 64) {
        // Load K (transposed, d-major) and V (natural) tiles; zero-fill tail
#pragma unroll
        for (int i = 0; i < 4; i++) {
            int f4 = tid + i * 256;
            int r = f4 >> 4;
            int d = (f4 & 15) << 2;
            int kg = kb + r;
            float4 kv = make_float4(0.f, 0.f, 0.f, 0.f);
            float4 vv = make_float4(0.f, 0.f, 0.f, 0.f);
            if (kg < span_hi) {
                kv = *(const float4*)(K + (size_t)kg * kE + hcol + d);
                vv = *(const float4*)(V + (size_t)kg * kE + hcol + d);
            }
            Ks[(d + 0) * 64 + r] = kv.x;
            Ks[(d + 1) * 64 + r] = kv.y;
            Ks[(d + 2) * 64 + r] = kv.z;
            Ks[(d + 3) * 64 + r] = kv.w;
            *(float4*)&Vs[r * 64 + d] = vv;
        }
        __syncthreads();

        // S = Q K^T (4x4 per thread)
        float s[4][4];
#pragma unroll
        for (int i = 0; i < 4; i++)
#pragma unroll
            for (int j = 0; j < 4; j++) s[i][j] = 0.0f;

#pragma unroll
        for (int d = 0; d < 64; d++) {
            float a[4], b[4];
            *(float4*)a = *(const float4*)&Qs[d * 64 + ty * 4];
            *(float4*)b = *(const float4*)&Ks[d * 64 + tx * 4];
#pragma unroll
            for (int i = 0; i < 4; i++)
#pragma unroll
                for (int j = 0; j < 4; j++)
                    s[i][j] = fmaf(a[i], b[j], s[i][j]);
        }

        // Mask + online softmax (per row; row group = 16 lanes, shfl width 16)
#pragma unroll
        for (int i = 0; i < 4; i++) {
#pragma unroll
            for (int j = 0; j < 4; j++) {
                int kg = kb + tx * 4 + j;
                if (kg < row_lo[i] || kg >= row_hi[i]) s[i][j] = -1e30f;
            }
            float rm = fmaxf(fmaxf(s[i][0], s[i][1]), fmaxf(s[i][2], s[i][3]));
            rm = fmaxf(rm, __shfl_xor_sync(0xffffffffu, rm, 8));
            rm = fmaxf(rm, __shfl_xor_sync(0xffffffffu, rm, 4));
            rm = fmaxf(rm, __shfl_xor_sync(0xffffffffu, rm, 2));
            rm = fmaxf(rm, __shfl_xor_sync(0xffffffffu, rm, 1));

            float mn = fmaxf(m[i], rm);
            float c = __expf(m[i] - mn);   // finite sentinel: never NaN
            float p[4], rs = 0.0f;
#pragma unroll
            for (int j = 0; j < 4; j++) {
                p[j] = (s[i][j] <= -1e29f) ? 0.0f : __expf(s[i][j] - mn);
                rs += p[j];
            }
            rs += __shfl_xor_sync(0xffffffffu, rs, 8);
            rs += __shfl_xor_sync(0xffffffffu, rs, 4);
            rs += __shfl_xor_sync(0xffffffffu, rs, 2);
            rs += __shfl_xor_sync(0xffffffffu, rs, 1);

            l[i] = l[i] * c + rs;
            m[i] = mn;
#pragma unroll
            for (int j = 0; j < 4; j++) o[i][j] *= c;

            *(float4*)&Ps[(ty * 4 + i) * 68 + tx * 4] =
                make_float4(p[0], p[1], p[2], p[3]);
        }
        __syncthreads();

        // O += P @ V
#pragma unroll
        for (int k = 0; k < 64; k++) {
            float b[4];
            *(float4*)b = *(const float4*)&Vs[k * 64 + tx * 4];
#pragma unroll
            for (int i = 0; i < 4; i++) {
                float a = Ps[(ty * 4 + i) * 68 + k];
#pragma unroll
                for (int j = 0; j < 4; j++)
                    o[i][j] = fmaf(a, b[j], o[i][j]);
            }
        }
        __syncthreads();
    }

    // Normalize and write
#pragma unroll
    for (int i = 0; i < 4; i++) {
        float inv = 1.0f / l[i];
        float4 v = make_float4(o[i][0] * inv, o[i][1] * inv,
                               o[i][2] * inv, o[i][3] * inv);
        *(float4*)(Out + (size_t)(q0 + ty * 4 + i) * kE + hcol + tx * 4) = v;
    }
}

// ---------------------------------------------------------------------------
extern "C" void kernel_launch(void* const* d_in, const int* in_sizes, int n_in,
                              void* d_out, int out_size) {
    const float* hs = (const float*)d_in[0];
    const int* cu   = (const int*)d_in[1];
    const float* Wq = (const float*)d_in[2];
    const float* bq = (const float*)d_in[3];
    const float* Wk = (const float*)d_in[4];
    const float* bk = (const float*)d_in[5];
    const float* Wv = (const float*)d_in[6];
    const float* bv = (const float*)d_in[7];
    const float* Wo = (const float*)d_in[8];
    const float* bo = (const float*)d_in[9];
    float* out = (float*)d_out;

    float *q, *k, *v, *attn;
    cudaGetSymbolAddress((void**)&q, g_q);
    cudaGetSymbolAddress((void**)&k, g_k);
    cudaGetSymbolAddress((void**)&v, g_v);
    cudaGetSymbolAddress((void**)&attn, g_attn);

    cudaFuncSetAttribute(varlen_attn,
                         cudaFuncAttributeMaxDynamicSharedMemorySize,
                         ATTN_SMEM_BYTES);

    dim3 gblk(256);
    dim3 ggrid(kE / 128, kT / 128);
    gemm_nt_bias<<<ggrid, gblk>>>(hs, Wq, bq, q);
    gemm_nt_bias<<<ggrid, gblk>>>(hs, Wk, bk, k);
    gemm_nt_bias<<<ggrid, gblk>>>(hs, Wv, bv, v);

    varlen_attn<<<dim3(kT / 64, kH), 256, ATTN_SMEM_BYTES>>>(q, k, v, cu, attn);

    gemm_nt_bias<<<ggrid, gblk>>>(attn, Wo, bo, out);
}

// round 3
// speedup vs baseline: 1.6777x; 1.6777x over previous
#include <cuda_runtime.h>
#include <cuda_bf16.h>
#include <math.h>
#include <cstdint>

// Problem constants
#define kT 4096
#define kE 1024
#define kH 16
#define kD 64

// ---------------------------------------------------------------------------
// Scratch (__device__ globals; allocation-free rule)
// ---------------------------------------------------------------------------
__device__ float g_q[kT * kE];
__device__ float g_k[kT * kE];
__device__ float g_v[kT * kE];
__device__ float g_attn[kT * kE];

__device__ __nv_bfloat16 g_Xh[kT * kE];
__device__ __nv_bfloat16 g_Xl[kT * kE];
__device__ __nv_bfloat16 g_Wh[4][kE * kE];  // q,k,v,o
__device__ __nv_bfloat16 g_Wl[4][kE * kE];
__device__ __nv_bfloat16 g_Ah[kT * kE];     // attn-output split
__device__ __nv_bfloat16 g_Al[kT * kE];

// ---------------------------------------------------------------------------
// Helpers: plain-PTX only (compute_103 target; NO tcgen05 / arch-specific ops)
// ---------------------------------------------------------------------------
__device__ __forceinline__ uint32_t smem_u32(const void* p) {
    uint32_t a;
    asm("{ .reg .u64 t; cvta.to.shared.u64 t, %1; cvt.u32.u64 %0, t; }"
        : "=r"(a) : "l"(p));
    return a;
}

__device__ __forceinline__ void ldsm_x4(uint32_t& r0, uint32_t& r1,
                                        uint32_t& r2, uint32_t& r3,
                                        uint32_t addr) {
    asm volatile("ldmatrix.sync.aligned.m8n8.x4.shared.b16 {%0,%1,%2,%3}, [%4];"
                 : "=r"(r0), "=r"(r1), "=r"(r2), "=r"(r3) : "r"(addr));
}

__device__ __forceinline__ void mma_bf16(float& d0, float& d1, float& d2, float& d3,
                                         uint32_t a0, uint32_t a1, uint32_t a2,
                                         uint32_t a3, uint32_t b0, uint32_t b1) {
    asm volatile(
        "mma.sync.aligned.m16n8k16.row.col.f32.bf16.bf16.f32 "
        "{%0,%1,%2,%3}, {%4,%5,%6,%7}, {%8,%9}, {%0,%1,%2,%3};"
        : "+f"(d0), "+f"(d1), "+f"(d2), "+f"(d3)
        : "r"(a0), "r"(a1), "r"(a2), "r"(a3), "r"(b0), "r"(b1));
}

// ---------------------------------------------------------------------------
// Elementwise split: fp32 -> (bf16 hi, bf16 lo), lo = bf16(x - float(hi))
// ---------------------------------------------------------------------------
__global__ void split_bf16(const float* __restrict__ in,
                           __nv_bfloat16* __restrict__ hi,
                           __nv_bfloat16* __restrict__ lo, int n) {
    int i = (blockIdx.x * blockDim.x + threadIdx.x) * 4;
    if (i >= n) return;
    float4 x = *(const float4*)(in + i);
    __nv_bfloat16 h0 = __float2bfloat16(x.x);
    __nv_bfloat16 h1 = __float2bfloat16(x.y);
    __nv_bfloat16 h2 = __float2bfloat16(x.z);
    __nv_bfloat16 h3 = __float2bfloat16(x.w);
    __nv_bfloat16 l0 = __float2bfloat16(x.x - __bfloat162float(h0));
    __nv_bfloat16 l1 = __float2bfloat16(x.y - __bfloat162float(h1));
    __nv_bfloat16 l2 = __float2bfloat16(x.z - __bfloat162float(h2));
    __nv_bfloat16 l3 = __float2bfloat16(x.w - __bfloat162float(h3));
    uint2 ph, pl;
    ph.x = ((uint32_t)__bfloat16_as_ushort(h1) << 16) | __bfloat16_as_ushort(h0);
    ph.y = ((uint32_t)__bfloat16_as_ushort(h3) << 16) | __bfloat16_as_ushort(h2);
    pl.x = ((uint32_t)__bfloat16_as_ushort(l1) << 16) | __bfloat16_as_ushort(l0);
    pl.y = ((uint32_t)__bfloat16_as_ushort(l3) << 16) | __bfloat16_as_ushort(l2);
    *(uint2*)(hi + i) = ph;
    *(uint2*)(lo + i) = pl;
}

// ---------------------------------------------------------------------------
// Warp-MMA split-bf16 GEMM-NT + bias.
// Y[m,n] = sum_k X[m,k]*W[n,k] + b[n].  M=4096, N=1024, K=1024.
// CTA 128x128, 8 warps (4m x 2n), warp tile 32x64, K-chunk 32.
// Per K16 step: D += Ah*Bh + Ah*Bl + Al*Bh  (mma.sync m16n8k16 bf16).
// smem padded stride 40 bf16 (80 B) -> conflict-light ldmatrix, no swizzle.
// ---------------------------------------------------------------------------
#define KCH 32
#define ASTR 40  // bf16 units

__global__ __launch_bounds__(256, 2)
void gemm_mma_split(const __nv_bfloat16* __restrict__ Ahg,
                    const __nv_bfloat16* __restrict__ Alg,
                    const __nv_bfloat16* __restrict__ Bhg,
                    const __nv_bfloat16* __restrict__ Blg,
                    const float* __restrict__ bias, float* __restrict__ Y) {
    __shared__ __nv_bfloat16 sAh[128 * ASTR];
    __shared__ __nv_bfloat16 sAl[128 * ASTR];
    __shared__ __nv_bfloat16 sBh[128 * ASTR];
    __shared__ __nv_bfloat16 sBl[128 * ASTR];

    const int tid = threadIdx.x;
    const int wid = tid >> 5;
    const int lid = tid & 31;
    const int wm = (wid & 3) * 32;   // warp m offset in tile
    const int wn = (wid >> 2) * 64;  // warp n offset in tile
    const int row0 = blockIdx.y * 128;
    const int col0 = blockIdx.x * 128;

    const uint32_t uAh = smem_u32(sAh);
    const uint32_t uAl = smem_u32(sAl);
    const uint32_t uBh = smem_u32(sBh);
    const uint32_t uBl = smem_u32(sBl);

    float acc[2][8][4];
#pragma unroll
    for (int i = 0; i < 2; i++)
#pragma unroll
        for (int j = 0; j < 8; j++)
#pragma unroll
            for (int c = 0; c < 4; c++) acc[i][j][c] = 0.0f;

    // ldmatrix per-lane row addressing (bytes)
    const int lrow = lid & 15;
    const int lkhalf = (lid >> 4) * 8;         // A: k half select
    const int bn = (lid >> 4) * 8 + (lid & 7); // B: n row within pair
    const int bk = ((lid >> 3) & 1) * 8;       // B: k half select

    for (int k0 = 0; k0 < kE; k0 += KCH) {
        // Load 4 tiles [128 x 32 bf16] each; 512 uint4 per tile, 2 per thread.
#pragma unroll
        for (int i = 0; i < 2; i++) {
            int f = tid + i * 256;     // 0..511
            int r = f >> 2;            // 0..127
            int c8 = (f & 3) * 8;      // 0,8,16,24
            int so = r * ASTR + c8;
            size_t ga = (size_t)(row0 + r) * kE + k0 + c8;
            size_t gb = (size_t)(col0 + r) * kE + k0 + c8;
            *(uint4*)(sAh + so) = *(const uint4*)(Ahg + ga);
            *(uint4*)(sAl + so) = *(const uint4*)(Alg + ga);
            *(uint4*)(sBh + so) = *(const uint4*)(Bhg + gb);
            *(uint4*)(sBl + so) = *(const uint4*)(Blg + gb);
        }
        __syncthreads();

#pragma unroll
        for (int kk = 0; kk < KCH; kk += 16) {
            // A fragments: 2 m-tiles, hi & lo
            uint32_t ah[2][4], al[2][4];
#pragma unroll
            for (int i = 0; i < 2; i++) {
                uint32_t off = (uint32_t)((wm + i * 16 + lrow) * ASTR + kk + lkhalf) * 2;
                ldsm_x4(ah[i][0], ah[i][1], ah[i][2], ah[i][3], uAh + off);
                ldsm_x4(al[i][0], al[i][1], al[i][2], al[i][3], uAl + off);
            }
            // B fragments in pairs of n-tiles
#pragma unroll
            for (int p = 0; p < 4; p++) {
                uint32_t boff = (uint32_t)((wn + p * 16 + bn) * ASTR + kk + bk) * 2;
                uint32_t bh0, bh1, bh2, bh3, bl0, bl1, bl2, bl3;
                ldsm_x4(bh0, bh1, bh2, bh3, uBh + boff);
                ldsm_x4(bl0, bl1, bl2, bl3, uBl + boff);
#pragma unroll
                for (int i = 0; i < 2; i++) {
                    float* d0 = acc[i][p * 2];
                    float* d1 = acc[i][p * 2 + 1];
                    mma_bf16(d0[0], d0[1], d0[2], d0[3],
                             ah[i][0], ah[i][1], ah[i][2], ah[i][3], bh0, bh1);
                    mma_bf16(d0[0], d0[1], d0[2], d0[3],
                             ah[i][0], ah[i][1], ah[i][2], ah[i][3], bl0, bl1);
                    mma_bf16(d0[0], d0[1], d0[2], d0[3],
                             al[i][0], al[i][1], al[i][2], al[i][3], bh0, bh1);
                    mma_bf16(d1[0], d1[1], d1[2], d1[3],
                             ah[i][0], ah[i][1], ah[i][2], ah[i][3], bh2, bh3);
                    mma_bf16(d1[0], d1[1], d1[2], d1[3],
                             ah[i][0], ah[i][1], ah[i][2], ah[i][3], bl2, bl3);
                    mma_bf16(d1[0], d1[1], d1[2], d1[3],
                             al[i][0], al[i][1], al[i][2], al[i][3], bh2, bh3);
                }
            }
        }
        __syncthreads();
    }

    // Epilogue: D layout m16n8: d0,d1 -> (row, col..col+1), d2,d3 -> row+8.
    const int erow = lid >> 2;
    const int ecol = (lid & 3) * 2;
#pragma unroll
    for (int i = 0; i < 2; i++) {
        int r = row0 + wm + i * 16 + erow;
#pragma unroll
        for (int j = 0; j < 8; j++) {
            int c = col0 + wn + j * 8 + ecol;
            float b0 = bias[c], b1 = bias[c + 1];
            float2 v0 = make_float2(acc[i][j][0] + b0, acc[i][j][1] + b1);
            float2 v1 = make_float2(acc[i][j][2] + b0, acc[i][j][3] + b1);
            *(float2*)(Y + (size_t)r * kE + c) = v0;
            *(float2*)(Y + (size_t)(r + 8) * kE + c) = v1;
        }
    }
}

// ---------------------------------------------------------------------------
// Varlen flash attention (unchanged; known correct).
// ---------------------------------------------------------------------------
#define ATTN_SMEM_BYTES (3 * 4096 * 4 + 64 * 68 * 4 + 2 * 64 * 4)

__global__ __launch_bounds__(256, 1)
void varlen_attn(const float* __restrict__ Q, const float* __restrict__ K,
                 const float* __restrict__ V, const int* __restrict__ cu,
                 float* __restrict__ Out) {
    extern __shared__ float sm[];
    float* Qs = sm;
    float* Ks = sm + 4096;
    float* Vs = sm + 8192;
    float* Ps = sm + 12288;
    int* s_lo = (int*)(sm + 12288 + 64 * 68);
    int* s_hi = s_lo + 64;

    const int tid = threadIdx.x;
    const int tx = tid & 15;
    const int ty = tid >> 4;
    const int q0 = blockIdx.x * 64;
    const int hcol = blockIdx.y * kD;

    if (tid < 64) {
        int r = q0 + tid;
        int lo = 0, hi = kT;
#pragma unroll
        for (int s = 0; s < 8; s++) {
            int a = cu[s], b = cu[s + 1];
            if (r >= a && r < b) { lo = a; hi = b; }
        }
        s_lo[tid] = lo;
        s_hi[tid] = hi;
    }

#pragma unroll
    for (int i = 0; i < 4; i++) {
        int f4 = tid + i * 256;
        int r = f4 >> 4;
        int d = (f4 & 15) << 2;
        float4 qv = *(const float4*)(Q + (size_t)(q0 + r) * kE + hcol + d);
        Qs[(d + 0) * 64 + r] = qv.x * 0.125f;
        Qs[(d + 1) * 64 + r] = qv.y * 0.125f;
        Qs[(d + 2) * 64 + r] = qv.z * 0.125f;
        Qs[(d + 3) * 64 + r] = qv.w * 0.125f;
    }
    __syncthreads();

    int row_lo[4], row_hi[4];
#pragma unroll
    for (int i = 0; i < 4; i++) {
        row_lo[i] = s_lo[ty * 4 + i];
        row_hi[i] = s_hi[ty * 4 + i];
    }
    const int span_lo = s_lo[0];
    const int span_hi = s_hi[63];

    float m[4], l[4], o[4][4];
#pragma unroll
    for (int i = 0; i < 4; i++) {
        m[i] = -1e30f;
        l[i] = 0.0f;
#pragma unroll
        for (int j = 0; j < 4; j++) o[i][j] = 0.0f;
    }

    for (int kb = span_lo; kb < span_hi; kb += 64) {
#pragma unroll
        for (int i = 0; i < 4; i++) {
            int f4 = tid + i * 256;
            int r = f4 >> 4;
            int d = (f4 & 15) << 2;
            int kg = kb + r;
            float4 kv = make_float4(0.f, 0.f, 0.f, 0.f);
            float4 vv = make_float4(0.f, 0.f, 0.f, 0.f);
            if (kg < span_hi) {
                kv = *(const float4*)(K + (size_t)kg * kE + hcol + d);
                vv = *(const float4*)(V + (size_t)kg * kE + hcol + d);
            }
            Ks[(d + 0) * 64 + r] = kv.x;
            Ks[(d + 1) * 64 + r] = kv.y;
            Ks[(d + 2) * 64 + r] = kv.z;
            Ks[(d + 3) * 64 + r] = kv.w;
            *(float4*)&Vs[r * 64 + d] = vv;
        }
        __syncthreads();

        float s[4][4];
#pragma unroll
        for (int i = 0; i < 4; i++)
#pragma unroll
            for (int j = 0; j < 4; j++) s[i][j] = 0.0f;

#pragma unroll
        for (int d = 0; d < 64; d++) {
            float a[4], b[4];
            *(float4*)a = *(const float4*)&Qs[d * 64 + ty * 4];
            *(float4*)b = *(const float4*)&Ks[d * 64 + tx * 4];
#pragma unroll
            for (int i = 0; i < 4; i++)
#pragma unroll
                for (int j = 0; j < 4; j++)
                    s[i][j] = fmaf(a[i], b[j], s[i][j]);
        }

#pragma unroll
        for (int i = 0; i < 4; i++) {
#pragma unroll
            for (int j = 0; j < 4; j++) {
                int kg = kb + tx * 4 + j;
                if (kg < row_lo[i] || kg >= row_hi[i]) s[i][j] = -1e30f;
            }
            float rm = fmaxf(fmaxf(s[i][0], s[i][1]), fmaxf(s[i][2], s[i][3]));
            rm = fmaxf(rm, __shfl_xor_sync(0xffffffffu, rm, 8));
            rm = fmaxf(rm, __shfl_xor_sync(0xffffffffu, rm, 4));
            rm = fmaxf(rm, __shfl_xor_sync(0xffffffffu, rm, 2));
            rm = fmaxf(rm, __shfl_xor_sync(0xffffffffu, rm, 1));

            float mn = fmaxf(m[i], rm);
            float c = __expf(m[i] - mn);
            float p[4], rs = 0.0f;
#pragma unroll
            for (int j = 0; j < 4; j++) {
                p[j] = (s[i][j] <= -1e29f) ? 0.0f : __expf(s[i][j] - mn);
                rs += p[j];
            }
            rs += __shfl_xor_sync(0xffffffffu, rs, 8);
            rs += __shfl_xor_sync(0xffffffffu, rs, 4);
            rs += __shfl_xor_sync(0xffffffffu, rs, 2);
            rs += __shfl_xor_sync(0xffffffffu, rs, 1);

            l[i] = l[i] * c + rs;
            m[i] = mn;
#pragma unroll
            for (int j = 0; j < 4; j++) o[i][j] *= c;

            *(float4*)&Ps[(ty * 4 + i) * 68 + tx * 4] =
                make_float4(p[0], p[1], p[2], p[3]);
        }
        __syncthreads();

#pragma unroll
        for (int k = 0; k < 64; k++) {
            float b[4];
            *(float4*)b = *(const float4*)&Vs[k * 64 + tx * 4];
#pragma unroll
            for (int i = 0; i < 4; i++) {
                float a = Ps[(ty * 4 + i) * 68 + k];
#pragma unroll
                for (int j = 0; j < 4; j++)
                    o[i][j] = fmaf(a, b[j], o[i][j]);
            }
        }
        __syncthreads();
    }

#pragma unroll
    for (int i = 0; i < 4; i++) {
        float inv = 1.0f / l[i];
        float4 v = make_float4(o[i][0] * inv, o[i][1] * inv,
                               o[i][2] * inv, o[i][3] * inv);
        *(float4*)(Out + (size_t)(q0 + ty * 4 + i) * kE + hcol + tx * 4) = v;
    }
}

// ---------------------------------------------------------------------------
extern "C" void kernel_launch(void* const* d_in, const int* in_sizes, int n_in,
                              void* d_out, int out_size) {
    const float* hs = (const float*)d_in[0];
    const int* cu   = (const int*)d_in[1];
    const float* W[4] = {(const float*)d_in[2], (const float*)d_in[4],
                         (const float*)d_in[6], (const float*)d_in[8]};
    const float* b[4] = {(const float*)d_in[3], (const float*)d_in[5],
                         (const float*)d_in[7], (const float*)d_in[9]};
    float* out = (float*)d_out;

    float *q, *k, *v, *attn;
    cudaGetSymbolAddress((void**)&q, g_q);
    cudaGetSymbolAddress((void**)&k, g_k);
    cudaGetSymbolAddress((void**)&v, g_v);
    cudaGetSymbolAddress((void**)&attn, g_attn);
    __nv_bfloat16 *Xh, *Xl, *Wh, *Wl, *Ah, *Al;
    cudaGetSymbolAddress((void**)&Xh, g_Xh);
    cudaGetSymbolAddress((void**)&Xl, g_Xl);
    cudaGetSymbolAddress((void**)&Wh, g_Wh);
    cudaGetSymbolAddress((void**)&Wl, g_Wl);
    cudaGetSymbolAddress((void**)&Ah, g_Ah);
    cudaGetSymbolAddress((void**)&Al, g_Al);

    cudaFuncSetAttribute(varlen_attn,
                         cudaFuncAttributeMaxDynamicSharedMemorySize,
                         ATTN_SMEM_BYTES);

    const int nX = kT * kE;   // 4.19M
    const int nW = kE * kE;   // 1.05M

    split_bf16<<<nX / 4 / 256, 256>>>(hs, Xh, Xl, nX);
    for (int i = 0; i < 4; i++)
        split_bf16<<<nW / 4 / 256, 256>>>(W[i], Wh + (size_t)i * nW,
                                          Wl + (size_t)i * nW, nW);

    dim3 ggrid(kE / 128, kT / 128);  // (8, 32)
    gemm_mma_split<<<ggrid, 256>>>(Xh, Xl, Wh + 0 * (size_t)nW,
                                   Wl + 0 * (size_t)nW, b[0], q);
    gemm_mma_split<<<ggrid, 256>>>(Xh, Xl, Wh + 1 * (size_t)nW,
                                   Wl + 1 * (size_t)nW, b[1], k);
    gemm_mma_split<<<ggrid, 256>>>(Xh, Xl, Wh + 2 * (size_t)nW,
                                   Wl + 2 * (size_t)nW, b[2], v);

    varlen_attn<<<dim3(kT / 64, kH), 256, ATTN_SMEM_BYTES>>>(q, k, v, cu, attn);

    split_bf16<<<nX / 4 / 256, 256>>>(attn, Ah, Al, nX);
    gemm_mma_split<<<ggrid, 256>>>(Ah, Al, Wh + 3 * (size_t)nW,
                                   Wl + 3 * (size_t)nW, b[3], out);
}

// round 4
// speedup vs baseline: 2.7079x; 1.6141x over previous
#include <cuda_runtime.h>
#include <cuda_bf16.h>
#include <math.h>
#include <cstdint>

// Problem constants
#define kT 4096
#define kE 1024
#define kH 16
#define kD 64

// ---------------------------------------------------------------------------
// Scratch (__device__ globals; allocation-free rule)
// ---------------------------------------------------------------------------
__device__ __nv_bfloat16 g_Xh[kT * kE];
__device__ __nv_bfloat16 g_Xl[kT * kE];
__device__ __nv_bfloat16 g_Wh[4][kE * kE];  // q,k,v,o
__device__ __nv_bfloat16 g_Wl[4][kE * kE];
__device__ __nv_bfloat16 g_Qh[kT * kE];
__device__ __nv_bfloat16 g_Ql[kT * kE];
__device__ __nv_bfloat16 g_Kh[kT * kE];
__device__ __nv_bfloat16 g_Kl[kT * kE];
__device__ __nv_bfloat16 g_Vh[kT * kE];
__device__ __nv_bfloat16 g_Vl[kT * kE];
__device__ __nv_bfloat16 g_Ah[kT * kE];     // attention output hi/lo
__device__ __nv_bfloat16 g_Al[kT * kE];

// ---------------------------------------------------------------------------
// Helpers (plain PTX, compute_103-safe: ldmatrix + mma.sync only)
// ---------------------------------------------------------------------------
__device__ __forceinline__ uint32_t smem_u32(const void* p) {
    uint32_t a;
    asm("{ .reg .u64 t; cvta.to.shared.u64 t, %1; cvt.u32.u64 %0, t; }"
        : "=r"(a) : "l"(p));
    return a;
}

__device__ __forceinline__ void ldsm_x4(uint32_t& r0, uint32_t& r1,
                                        uint32_t& r2, uint32_t& r3,
                                        uint32_t addr) {
    asm volatile("ldmatrix.sync.aligned.m8n8.x4.shared.b16 {%0,%1,%2,%3}, [%4];"
                 : "=r"(r0), "=r"(r1), "=r"(r2), "=r"(r3) : "r"(addr));
}

__device__ __forceinline__ void ldsm_x4_trans(uint32_t& r0, uint32_t& r1,
                                              uint32_t& r2, uint32_t& r3,
                                              uint32_t addr) {
    asm volatile("ldmatrix.sync.aligned.m8n8.x4.trans.shared.b16 {%0,%1,%2,%3}, [%4];"
                 : "=r"(r0), "=r"(r1), "=r"(r2), "=r"(r3) : "r"(addr));
}

__device__ __forceinline__ void mma_bf16(float& d0, float& d1, float& d2, float& d3,
                                         uint32_t a0, uint32_t a1, uint32_t a2,
                                         uint32_t a3, uint32_t b0, uint32_t b1) {
    asm volatile(
        "mma.sync.aligned.m16n8k16.row.col.f32.bf16.bf16.f32 "
        "{%0,%1,%2,%3}, {%4,%5,%6,%7}, {%8,%9}, {%0,%1,%2,%3};"
        : "+f"(d0), "+f"(d1), "+f"(d2), "+f"(d3)
        : "r"(a0), "r"(a1), "r"(a2), "r"(a3), "r"(b0), "r"(b1));
}

__device__ __forceinline__ uint32_t pack_bf16(float a, float b) {
    __nv_bfloat16 ha = __float2bfloat16(a);
    __nv_bfloat16 hb = __float2bfloat16(b);
    return ((uint32_t)__bfloat16_as_ushort(hb) << 16) | __bfloat16_as_ushort(ha);
}

// ---------------------------------------------------------------------------
// Elementwise split: fp32 -> (bf16 hi, bf16 lo), lo = bf16(x - float(hi))
// ---------------------------------------------------------------------------
__global__ void split_bf16(const float* __restrict__ in,
                           __nv_bfloat16* __restrict__ hi,
                           __nv_bfloat16* __restrict__ lo, int n) {
    int i = (blockIdx.x * blockDim.x + threadIdx.x) * 4;
    if (i >= n) return;
    float4 x = *(const float4*)(in + i);
    __nv_bfloat16 h0 = __float2bfloat16(x.x);
    __nv_bfloat16 h1 = __float2bfloat16(x.y);
    __nv_bfloat16 h2 = __float2bfloat16(x.z);
    __nv_bfloat16 h3 = __float2bfloat16(x.w);
    __nv_bfloat16 l0 = __float2bfloat16(x.x - __bfloat162float(h0));
    __nv_bfloat16 l1 = __float2bfloat16(x.y - __bfloat162float(h1));
    __nv_bfloat16 l2 = __float2bfloat16(x.z - __bfloat162float(h2));
    __nv_bfloat16 l3 = __float2bfloat16(x.w - __bfloat162float(h3));
    uint2 ph, pl;
    ph.x = ((uint32_t)__bfloat16_as_ushort(h1) << 16) | __bfloat16_as_ushort(h0);
    ph.y = ((uint32_t)__bfloat16_as_ushort(h3) << 16) | __bfloat16_as_ushort(h2);
    pl.x = ((uint32_t)__bfloat16_as_ushort(l1) << 16) | __bfloat16_as_ushort(l0);
    pl.y = ((uint32_t)__bfloat16_as_ushort(l3) << 16) | __bfloat16_as_ushort(l2);
    *(uint2*)(hi + i) = ph;
    *(uint2*)(lo + i) = pl;
}

// ---------------------------------------------------------------------------
// Warp-MMA split-bf16 GEMM-NT + bias.
// Y[m,n] = sum_k X[m,k]*W[n,k] + b[n].  CTA 128x128, 8 warps, K-chunk 32.
// BF16OUT: write bf16 hi/lo pair instead of fp32.
// ---------------------------------------------------------------------------
#define KCH 32
#define ASTR 40  // bf16 units

template <bool BF16OUT>
__global__ __launch_bounds__(256, 2)
void gemm_mma_split(const __nv_bfloat16* __restrict__ Ahg,
                    const __nv_bfloat16* __restrict__ Alg,
                    const __nv_bfloat16* __restrict__ Bhg,
                    const __nv_bfloat16* __restrict__ Blg,
                    const float* __restrict__ bias,
                    float* __restrict__ Yf,
                    __nv_bfloat16* __restrict__ Yh,
                    __nv_bfloat16* __restrict__ Yl) {
    __shared__ __nv_bfloat16 sAh[128 * ASTR];
    __shared__ __nv_bfloat16 sAl[128 * ASTR];
    __shared__ __nv_bfloat16 sBh[128 * ASTR];
    __shared__ __nv_bfloat16 sBl[128 * ASTR];

    const int tid = threadIdx.x;
    const int wid = tid >> 5;
    const int lid = tid & 31;
    const int wm = (wid & 3) * 32;
    const int wn = (wid >> 2) * 64;
    const int row0 = blockIdx.y * 128;
    const int col0 = blockIdx.x * 128;

    const uint32_t uAh = smem_u32(sAh);
    const uint32_t uAl = smem_u32(sAl);
    const uint32_t uBh = smem_u32(sBh);
    const uint32_t uBl = smem_u32(sBl);

    float acc[2][8][4];
#pragma unroll
    for (int i = 0; i < 2; i++)
#pragma unroll
        for (int j = 0; j < 8; j++)
#pragma unroll
            for (int c = 0; c < 4; c++) acc[i][j][c] = 0.0f;

    const int lrow = lid & 15;
    const int lkhalf = (lid >> 4) * 8;
    const int bn = (lid >> 4) * 8 + (lid & 7);
    const int bk = ((lid >> 3) & 1) * 8;

    for (int k0 = 0; k0 < kE; k0 += KCH) {
#pragma unroll
        for (int i = 0; i < 2; i++) {
            int f = tid + i * 256;
            int r = f >> 2;
            int c8 = (f & 3) * 8;
            int so = r * ASTR + c8;
            size_t ga = (size_t)(row0 + r) * kE + k0 + c8;
            size_t gb = (size_t)(col0 + r) * kE + k0 + c8;
            *(uint4*)(sAh + so) = *(const uint4*)(Ahg + ga);
            *(uint4*)(sAl + so) = *(const uint4*)(Alg + ga);
            *(uint4*)(sBh + so) = *(const uint4*)(Bhg + gb);
            *(uint4*)(sBl + so) = *(const uint4*)(Blg + gb);
        }
        __syncthreads();

#pragma unroll
        for (int kk = 0; kk < KCH; kk += 16) {
            uint32_t ah[2][4], al[2][4];
#pragma unroll
            for (int i = 0; i < 2; i++) {
                uint32_t off = (uint32_t)((wm + i * 16 + lrow) * ASTR + kk + lkhalf) * 2;
                ldsm_x4(ah[i][0], ah[i][1], ah[i][2], ah[i][3], uAh + off);
                ldsm_x4(al[i][0], al[i][1], al[i][2], al[i][3], uAl + off);
            }
#pragma unroll
            for (int p = 0; p < 4; p++) {
                uint32_t boff = (uint32_t)((wn + p * 16 + bn) * ASTR + kk + bk) * 2;
                uint32_t bh0, bh1, bh2, bh3, bl0, bl1, bl2, bl3;
                ldsm_x4(bh0, bh1, bh2, bh3, uBh + boff);
                ldsm_x4(bl0, bl1, bl2, bl3, uBl + boff);
#pragma unroll
                for (int i = 0; i < 2; i++) {
                    float* d0 = acc[i][p * 2];
                    float* d1 = acc[i][p * 2 + 1];
                    mma_bf16(d0[0], d0[1], d0[2], d0[3],
                             ah[i][0], ah[i][1], ah[i][2], ah[i][3], bh0, bh1);
                    mma_bf16(d0[0], d0[1], d0[2], d0[3],
                             ah[i][0], ah[i][1], ah[i][2], ah[i][3], bl0, bl1);
                    mma_bf16(d0[0], d0[1], d0[2], d0[3],
                             al[i][0], al[i][1], al[i][2], al[i][3], bh0, bh1);
                    mma_bf16(d1[0], d1[1], d1[2], d1[3],
                             ah[i][0], ah[i][1], ah[i][2], ah[i][3], bh2, bh3);
                    mma_bf16(d1[0], d1[1], d1[2], d1[3],
                             ah[i][0], ah[i][1], ah[i][2], ah[i][3], bl2, bl3);
                    mma_bf16(d1[0], d1[1], d1[2], d1[3],
                             al[i][0], al[i][1], al[i][2], al[i][3], bh2, bh3);
                }
            }
        }
        __syncthreads();
    }

    const int erow = lid >> 2;
    const int ecol = (lid & 3) * 2;
#pragma unroll
    for (int i = 0; i < 2; i++) {
        int r = row0 + wm + i * 16 + erow;
#pragma unroll
        for (int j = 0; j < 8; j++) {
            int c = col0 + wn + j * 8 + ecol;
            float b0 = bias[c], b1 = bias[c + 1];
            float v00 = acc[i][j][0] + b0, v01 = acc[i][j][1] + b1;
            float v10 = acc[i][j][2] + b0, v11 = acc[i][j][3] + b1;
            if (BF16OUT) {
                __nv_bfloat16 h00 = __float2bfloat16(v00);
                __nv_bfloat16 h01 = __float2bfloat16(v01);
                __nv_bfloat16 h10 = __float2bfloat16(v10);
                __nv_bfloat16 h11 = __float2bfloat16(v11);
                uint32_t ph0 = ((uint32_t)__bfloat16_as_ushort(h01) << 16) |
                               __bfloat16_as_ushort(h00);
                uint32_t ph1 = ((uint32_t)__bfloat16_as_ushort(h11) << 16) |
                               __bfloat16_as_ushort(h10);
                uint32_t pl0 = pack_bf16(v00 - __bfloat162float(h00),
                                         v01 - __bfloat162float(h01));
                uint32_t pl1 = pack_bf16(v10 - __bfloat162float(h10),
                                         v11 - __bfloat162float(h11));
                *(uint32_t*)(Yh + (size_t)r * kE + c) = ph0;
                *(uint32_t*)(Yh + (size_t)(r + 8) * kE + c) = ph1;
                *(uint32_t*)(Yl + (size_t)r * kE + c) = pl0;
                *(uint32_t*)(Yl + (size_t)(r + 8) * kE + c) = pl1;
            } else {
                *(float2*)(Yf + (size_t)r * kE + c) = make_float2(v00, v01);
                *(float2*)(Yf + (size_t)(r + 8) * kE + c) = make_float2(v10, v11);
            }
        }
    }
}

// ---------------------------------------------------------------------------
// Varlen flash attention with mma.sync (bf16 split inputs, fp32 softmax).
// Grid (kT/64, kH), 128 threads = 4 warps; warp w handles q rows w*16..+16.
// S = Qh*Kh + Qh*Kl + Ql*Kh;  O += Ph*Vh + Ph*Vl + Pl*Vh.
// ---------------------------------------------------------------------------
#define QSTR 72  // bf16 stride for 64-wide tiles
// bf16 units: Qh 0, Ql 4608, Kh 9216, Kl 13824, Vh 18432, Vl 23040, end 27648
#define ATTN_SMEM (27648 * 2 + 2 * 64 * 4)

__global__ __launch_bounds__(128)
void attn_mma(const __nv_bfloat16* __restrict__ Qhg,
              const __nv_bfloat16* __restrict__ Qlg,
              const __nv_bfloat16* __restrict__ Khg,
              const __nv_bfloat16* __restrict__ Klg,
              const __nv_bfloat16* __restrict__ Vhg,
              const __nv_bfloat16* __restrict__ Vlg,
              const int* __restrict__ cu,
              __nv_bfloat16* __restrict__ Oh,
              __nv_bfloat16* __restrict__ Ol) {
    extern __shared__ __nv_bfloat16 sb[];
    __nv_bfloat16* sQh = sb;
    __nv_bfloat16* sQl = sb + 4608;
    __nv_bfloat16* sKh = sb + 9216;
    __nv_bfloat16* sKl = sb + 13824;
    __nv_bfloat16* sVh = sb + 18432;
    __nv_bfloat16* sVl = sb + 23040;
    int* s_lo = (int*)(sb + 27648);
    int* s_hi = s_lo + 64;

    const int tid = threadIdx.x;
    const int wid = tid >> 5;
    const int lid = tid & 31;
    const int q0 = blockIdx.x * 64;
    const int hcol = blockIdx.y * kD;
    const int wm = wid * 16;

    const uint32_t uQh = smem_u32(sQh);
    const uint32_t uQl = smem_u32(sQl);
    const uint32_t uKh = smem_u32(sKh);
    const uint32_t uKl = smem_u32(sKl);
    const uint32_t uVh = smem_u32(sVh);
    const uint32_t uVl = smem_u32(sVl);

    // Per-row segment bounds
    if (tid < 64) {
        int r = q0 + tid;
        int lo = 0, hi = kT;
#pragma unroll
        for (int s = 0; s < 8; s++) {
            int a = cu[s], b = cu[s + 1];
            if (r >= a && r < b) { lo = a; hi = b; }
        }
        s_lo[tid] = lo;
        s_hi[tid] = hi;
    }

    // Load Q tile: 64 rows x 64 bf16 per matrix (8 uint4/row)
#pragma unroll
    for (int i = 0; i < 4; i++) {
        int f = tid + i * 128;          // 0..511
        int r = f >> 3;
        int c8 = (f & 7) * 8;
        size_t g = (size_t)(q0 + r) * kE + hcol + c8;
        int so = r * QSTR + c8;
        *(uint4*)(sQh + so) = *(const uint4*)(Qhg + g);
        *(uint4*)(sQl + so) = *(const uint4*)(Qlg + g);
    }
    __syncthreads();

    const int rrow = lid >> 2;            // 0..7
    int row_lo[2], row_hi[2];
    row_lo[0] = s_lo[wm + rrow];      row_hi[0] = s_hi[wm + rrow];
    row_lo[1] = s_lo[wm + rrow + 8];  row_hi[1] = s_hi[wm + rrow + 8];
    const int span_lo = s_lo[0];
    const int span_hi = s_hi[63];

    // ldmatrix lane addressing
    const int lrow = lid & 15;
    const int lkhalf = (lid >> 4) * 8;
    const int bn = (lid >> 4) * 8 + (lid & 7);
    const int bk = ((lid >> 3) & 1) * 8;
    // V trans tiles: tile = lid>>3, row-in-tile = lid&7
    const int vt = lid >> 3;
    const int vr = lid & 7;

    float m[2], l[2], o[8][4];
    m[0] = m[1] = -1e30f;
    l[0] = l[1] = 0.0f;
#pragma unroll
    for (int t = 0; t < 8; t++)
#pragma unroll
        for (int c = 0; c < 4; c++) o[t][c] = 0.0f;

    for (int kb = span_lo; kb < span_hi; kb += 64) {
        __syncthreads();   // prior iteration's V reads done
        // Load K, V tiles (zero-fill beyond span_hi)
#pragma unroll
        for (int i = 0; i < 4; i++) {
            int f = tid + i * 128;
            int r = f >> 3;
            int c8 = (f & 7) * 8;
            int kg = kb + r;
            uint4 z = make_uint4(0, 0, 0, 0);
            uint4 vkh = z, vkl = z, vvh = z, vvl = z;
            if (kg < span_hi) {
                size_t g = (size_t)kg * kE + hcol + c8;
                vkh = *(const uint4*)(Khg + g);
                vkl = *(const uint4*)(Klg + g);
                vvh = *(const uint4*)(Vhg + g);
                vvl = *(const uint4*)(Vlg + g);
            }
            int so = r * QSTR + c8;
            *(uint4*)(sKh + so) = vkh;
            *(uint4*)(sKl + so) = vkl;
            *(uint4*)(sVh + so) = vvh;
            *(uint4*)(sVl + so) = vvl;
        }
        __syncthreads();

        // ---- S = Q K^T ----
        float s[8][4];
#pragma unroll
        for (int t = 0; t < 8; t++)
#pragma unroll
            for (int c = 0; c < 4; c++) s[t][c] = 0.0f;

#pragma unroll
        for (int kc = 0; kc < 4; kc++) {
            uint32_t qh[4], ql[4];
            uint32_t aoff = (uint32_t)((wm + lrow) * QSTR + kc * 16 + lkhalf) * 2;
            ldsm_x4(qh[0], qh[1], qh[2], qh[3], uQh + aoff);
            ldsm_x4(ql[0], ql[1], ql[2], ql[3], uQl + aoff);
#pragma unroll
            for (int p = 0; p < 4; p++) {
                uint32_t boff = (uint32_t)((p * 16 + bn) * QSTR + kc * 16 + bk) * 2;
                uint32_t kh0, kh1, kh2, kh3, kl0, kl1, kl2, kl3;
                ldsm_x4(kh0, kh1, kh2, kh3, uKh + boff);
                ldsm_x4(kl0, kl1, kl2, kl3, uKl + boff);
                float* d0 = s[p * 2];
                float* d1 = s[p * 2 + 1];
                mma_bf16(d0[0], d0[1], d0[2], d0[3], qh[0], qh[1], qh[2], qh[3], kh0, kh1);
                mma_bf16(d0[0], d0[1], d0[2], d0[3], qh[0], qh[1], qh[2], qh[3], kl0, kl1);
                mma_bf16(d0[0], d0[1], d0[2], d0[3], ql[0], ql[1], ql[2], ql[3], kh0, kh1);
                mma_bf16(d1[0], d1[1], d1[2], d1[3], qh[0], qh[1], qh[2], qh[3], kh2, kh3);
                mma_bf16(d1[0], d1[1], d1[2], d1[3], qh[0], qh[1], qh[2], qh[3], kl2, kl3);
                mma_bf16(d1[0], d1[1], d1[2], d1[3], ql[0], ql[1], ql[2], ql[3], kh2, kh3);
            }
        }

        // ---- scale + mask + online softmax ----
        const int colb = (lid & 3) * 2;
#pragma unroll
        for (int i = 0; i < 2; i++) {
            float rm = -1e30f;
#pragma unroll
            for (int t = 0; t < 8; t++) {
                int kg0 = kb + t * 8 + colb;
                float v0 = s[t][2 * i] * 0.125f;
                float v1 = s[t][2 * i + 1] * 0.125f;
                if (kg0 < row_lo[i] || kg0 >= row_hi[i]) v0 = -1e30f;
                if (kg0 + 1 < row_lo[i] || kg0 + 1 >= row_hi[i]) v1 = -1e30f;
                s[t][2 * i] = v0;
                s[t][2 * i + 1] = v1;
                rm = fmaxf(rm, fmaxf(v0, v1));
            }
            rm = fmaxf(rm, __shfl_xor_sync(0xffffffffu, rm, 1));
            rm = fmaxf(rm, __shfl_xor_sync(0xffffffffu, rm, 2));

            float mn = fmaxf(m[i], rm);
            float c = __expf(m[i] - mn);
            float rs = 0.0f;
#pragma unroll
            for (int t = 0; t < 8; t++) {
                float v0 = s[t][2 * i];
                float v1 = s[t][2 * i + 1];
                float p0 = (v0 <= -1e29f) ? 0.0f : __expf(v0 - mn);
                float p1 = (v1 <= -1e29f) ? 0.0f : __expf(v1 - mn);
                s[t][2 * i] = p0;
                s[t][2 * i + 1] = p1;
                rs += p0 + p1;
            }
            rs += __shfl_xor_sync(0xffffffffu, rs, 1);
            rs += __shfl_xor_sync(0xffffffffu, rs, 2);

            l[i] = l[i] * c + rs;
            m[i] = mn;
#pragma unroll
            for (int t = 0; t < 8; t++) {
                o[t][2 * i] *= c;
                o[t][2 * i + 1] *= c;
            }
        }

        // ---- O += P V ----  (P split hi/lo from S regs, fragment reuse)
#pragma unroll
        for (int kc = 0; kc < 4; kc++) {
            int t0 = 2 * kc, t1 = 2 * kc + 1;
            uint32_t ph[4], pl[4];
            {
                __nv_bfloat16 h;
                float f0, f1;
                f0 = s[t0][0]; f1 = s[t0][1];
                ph[0] = pack_bf16(f0, f1);
                h = __float2bfloat16(f0); f0 -= __bfloat162float(h);
                h = __float2bfloat16(f1); f1 -= __bfloat162float(h);
                pl[0] = pack_bf16(f0, f1);
                f0 = s[t0][2]; f1 = s[t0][3];
                ph[1] = pack_bf16(f0, f1);
                h = __float2bfloat16(f0); f0 -= __bfloat162float(h);
                h = __float2bfloat16(f1); f1 -= __bfloat162float(h);
                pl[1] = pack_bf16(f0, f1);
                f0 = s[t1][0]; f1 = s[t1][1];
                ph[2] = pack_bf16(f0, f1);
                h = __float2bfloat16(f0); f0 -= __bfloat162float(h);
                h = __float2bfloat16(f1); f1 -= __bfloat162float(h);
                pl[2] = pack_bf16(f0, f1);
                f0 = s[t1][2]; f1 = s[t1][3];
                ph[3] = pack_bf16(f0, f1);
                h = __float2bfloat16(f0); f0 -= __bfloat162float(h);
                h = __float2bfloat16(f1); f1 -= __bfloat162float(h);
                pl[3] = pack_bf16(f0, f1);
            }
#pragma unroll
            for (int dp = 0; dp < 4; dp++) {
                // V trans ldmatrix: keys kc*16.., d cols dp*16..
                uint32_t voff = (uint32_t)((kc * 16 + (vt & 1) * 8 + vr) * QSTR +
                                           dp * 16 + (vt >> 1) * 8) * 2;
                uint32_t vh0, vh1, vh2, vh3, vl0, vl1, vl2, vl3;
                ldsm_x4_trans(vh0, vh1, vh2, vh3, uVh + voff);
                ldsm_x4_trans(vl0, vl1, vl2, vl3, uVl + voff);
                float* d0 = o[dp * 2];
                float* d1 = o[dp * 2 + 1];
                mma_bf16(d0[0], d0[1], d0[2], d0[3], ph[0], ph[1], ph[2], ph[3], vh0, vh1);
                mma_bf16(d0[0], d0[1], d0[2], d0[3], ph[0], ph[1], ph[2], ph[3], vl0, vl1);
                mma_bf16(d0[0], d0[1], d0[2], d0[3], pl[0], pl[1], pl[2], pl[3], vh0, vh1);
                mma_bf16(d1[0], d1[1], d1[2], d1[3], ph[0], ph[1], ph[2], ph[3], vh2, vh3);
                mma_bf16(d1[0], d1[1], d1[2], d1[3], ph[0], ph[1], ph[2], ph[3], vl2, vl3);
                mma_bf16(d1[0], d1[1], d1[2], d1[3], pl[0], pl[1], pl[2], pl[3], vh2, vh3);
            }
        }
    }

    // Normalize and write bf16 hi/lo
    float inv0 = 1.0f / l[0];
    float inv1 = 1.0f / l[1];
    const int colb = (lid & 3) * 2;
#pragma unroll
    for (int t = 0; t < 8; t++) {
        int col = hcol + t * 8 + colb;
        int r0 = q0 + wm + rrow;
        float v00 = o[t][0] * inv0, v01 = o[t][1] * inv0;
        float v10 = o[t][2] * inv1, v11 = o[t][3] * inv1;
        __nv_bfloat16 h00 = __float2bfloat16(v00);
        __nv_bfloat16 h01 = __float2bfloat16(v01);
        __nv_bfloat16 h10 = __float2bfloat16(v10);
        __nv_bfloat16 h11 = __float2bfloat16(v11);
        uint32_t ph0 = ((uint32_t)__bfloat16_as_ushort(h01) << 16) |
                       __bfloat16_as_ushort(h00);
        uint32_t ph1 = ((uint32_t)__bfloat16_as_ushort(h11) << 16) |
                       __bfloat16_as_ushort(h10);
        uint32_t pl0 = pack_bf16(v00 - __bfloat162float(h00),
                                 v01 - __bfloat162float(h01));
        uint32_t pl1 = pack_bf16(v10 - __bfloat162float(h10),
                                 v11 - __bfloat162float(h11));
        *(uint32_t*)(Oh + (size_t)r0 * kE + col) = ph0;
        *(uint32_t*)(Oh + (size_t)(r0 + 8) * kE + col) = ph1;
        *(uint32_t*)(Ol + (size_t)r0 * kE + col) = pl0;
        *(uint32_t*)(Ol + (size_t)(r0 + 8) * kE + col) = pl1;
    }
}

// ---------------------------------------------------------------------------
extern "C" void kernel_launch(void* const* d_in, const int* in_sizes, int n_in,
                              void* d_out, int out_size) {
    const float* hs = (const float*)d_in[0];
    const int* cu   = (const int*)d_in[1];
    const float* W[4] = {(const float*)d_in[2], (const float*)d_in[4],
                         (const float*)d_in[6], (const float*)d_in[8]};
    const float* b[4] = {(const float*)d_in[3], (const float*)d_in[5],
                         (const float*)d_in[7], (const float*)d_in[9]};
    float* out = (float*)d_out;

    __nv_bfloat16 *Xh, *Xl, *Wh, *Wl, *Qh, *Ql, *Kh, *Kl, *Vh, *Vl, *Ah, *Al;
    cudaGetSymbolAddress((void**)&Xh, g_Xh);
    cudaGetSymbolAddress((void**)&Xl, g_Xl);
    cudaGetSymbolAddress((void**)&Wh, g_Wh);
    cudaGetSymbolAddress((void**)&Wl, g_Wl);
    cudaGetSymbolAddress((void**)&Qh, g_Qh);
    cudaGetSymbolAddress((void**)&Ql, g_Ql);
    cudaGetSymbolAddress((void**)&Kh, g_Kh);
    cudaGetSymbolAddress((void**)&Kl, g_Kl);
    cudaGetSymbolAddress((void**)&Vh, g_Vh);
    cudaGetSymbolAddress((void**)&Vl, g_Vl);
    cudaGetSymbolAddress((void**)&Ah, g_Ah);
    cudaGetSymbolAddress((void**)&Al, g_Al);

    cudaFuncSetAttribute(attn_mma,
                         cudaFuncAttributeMaxDynamicSharedMemorySize, ATTN_SMEM);

    const int nX = kT * kE;
    const int nW = kE * kE;

    split_bf16<<<nX / 4 / 256, 256>>>(hs, Xh, Xl, nX);
    for (int i = 0; i < 4; i++)
        split_bf16<<<nW / 4 / 256, 256>>>(W[i], Wh + (size_t)i * nW,
                                          Wl + (size_t)i * nW, nW);

    dim3 ggrid(kE / 128, kT / 128);  // (8, 32)
    gemm_mma_split<true><<<ggrid, 256>>>(Xh, Xl, Wh + 0 * (size_t)nW,
                                         Wl + 0 * (size_t)nW, b[0],
                                         nullptr, Qh, Ql);
    gemm_mma_split<true><<<ggrid, 256>>>(Xh, Xl, Wh + 1 * (size_t)nW,
                                         Wl + 1 * (size_t)nW, b[1],
                                         nullptr, Kh, Kl);
    gemm_mma_split<true><<<ggrid, 256>>>(Xh, Xl, Wh + 2 * (size_t)nW,
                                         Wl + 2 * (size_t)nW, b[2],
                                         nullptr, Vh, Vl);

    attn_mma<<<dim3(kT / 64, kH), 128, ATTN_SMEM>>>(Qh, Ql, Kh, Kl, Vh, Vl,
                                                    cu, Ah, Al);

    gemm_mma_split<false><<<ggrid, 256>>>(Ah, Al, Wh + 3 * (size_t)nW,
                                          Wl + 3 * (size_t)nW, b[3],
                                          out, nullptr, nullptr);
}